// round 7
// baseline (speedup 1.0000x reference)
#include <cuda_runtime.h>
#include <cuda_fp16.h>
#include <math.h>

#define MAX_NE 100000
#define MAX_NR 1000
#define MAX_E  1000000
#define PACK_CAP 1310784   // E + 3*N_E padding + over-read guard

// ---------------- scratch ----------------
__device__ float  g_sh[MAX_NE];
__device__ float  g_st[MAX_NE];
__device__ float  g_sr[MAX_NR];
// fp16 P tables: [side(2)][chunk(4)][rel][64 halves]; h side 0..3, t side 4..7
__device__ __half g_P16[8 * MAX_NR * 64];
__device__ int    g_cnt_h[MAX_NE];
__device__ int    g_cnt_t[MAX_NE];
__device__ int    g_starts_h[MAX_NE + 1];  // PADDED exclusive starts (multiples of 4 edges)
__device__ int    g_starts_t[MAX_NE + 1];
__device__ int    g_cur_h[MAX_NE];
__device__ int    g_cur_t[MAX_NE];
__device__ float  g_sum_h[MAX_NE];         // softmax denominators (accumulated in k_place)
__device__ float  g_sum_t[MAX_NE];
__device__ float  g_inv_h[MAX_NE];
__device__ float  g_inv_t[MAX_NE];
// pad slots are NEVER written: BSS-zero => {z=0, off=0}, mathematically inert.
__device__ float2 g_pack_h[PACK_CAP];
__device__ float2 g_pack_t[PACK_CAP];
__device__ int    g_bsum[2][160];

// ---------------- fused attention scores + per-node scratch zeroing ----------------
__global__ void k_scores(const float4* __restrict__ xe, const float4* __restrict__ xr,
                         const float4* __restrict__ wah4, const float4* __restrict__ wat4,
                         const float4* __restrict__ war4, int n_e, int n_r) {
    int gw = (blockIdx.x * blockDim.x + threadIdx.x) >> 5;
    int lane = threadIdx.x & 31;
    if (gw < n_e) {
        float4 v = xe[(size_t)gw * 32 + lane];
        float4 a = wah4[lane];
        float4 b = wat4[lane];
        float da = v.x * a.x + v.y * a.y + v.z * a.z + v.w * a.w;
        float db = v.x * b.x + v.y * b.y + v.z * b.z + v.w * b.w;
#pragma unroll
        for (int o = 16; o > 0; o >>= 1) {
            da += __shfl_xor_sync(0xffffffffu, da, o);
            db += __shfl_xor_sync(0xffffffffu, db, o);
        }
        if (lane == 0) { g_sh[gw] = da; g_st[gw] = db; }
        else if (lane == 1) g_cnt_h[gw] = 0;
        else if (lane == 2) g_cnt_t[gw] = 0;
        else if (lane == 3) g_sum_h[gw] = 0.f;
        else if (lane == 4) g_sum_t[gw] = 0.f;
    } else if (gw < n_e + n_r) {
        int r = gw - n_e;
        float4 v = xr[r * 32 + lane];
        float4 a = war4[lane];
        float d = v.x * a.x + v.y * a.y + v.z * a.z + v.w * a.w;
#pragma unroll
        for (int o = 16; o > 0; o >>= 1) d += __shfl_xor_sync(0xffffffffu, d, o);
        if (lane == 0) g_sr[r] = d;
    }
}

// ---------------- fused relation pipeline: x_r -> hid -> msg -> P (fp16) ----------------
#define RPB 8
__global__ __launch_bounds__(256) void k_rgemm(const float* __restrict__ xr,
                                               const float* __restrict__ W1, const float* __restrict__ b1,
                                               const float* __restrict__ W2, const float* __restrict__ b2,
                                               const float* __restrict__ Wr, int n_r) {
    __shared__ float sx[RPB * 128];
    __shared__ float shid[RPB * 256];
    __shared__ float smsg[RPB * 128];
    __shared__ float wt[32 * 256];
    int r0 = blockIdx.x * RPB;
    int tid = threadIdx.x;

    for (int i = tid; i < RPB * 128; i += 256) {
        int rr = i >> 7, k = i & 127, r = r0 + rr;
        sx[i] = (r < n_r) ? xr[r * 128 + k] : 0.f;
    }

    // ---- hid = x @ W1 + b1 ----
    {
        int j = tid;
        float acc[RPB];
        float bj = b1[j];
#pragma unroll
        for (int u = 0; u < RPB; u++) acc[u] = bj;
        for (int k0 = 0; k0 < 128; k0 += 32) {
            __syncthreads();
            for (int i = tid; i < 8192; i += 256)
                wt[i] = W1[(k0 + (i >> 8)) * 256 + (i & 255)];
            __syncthreads();
#pragma unroll 8
            for (int kk = 0; kk < 32; kk++) {
                float w = wt[kk * 256 + j];
#pragma unroll
                for (int u = 0; u < RPB; u++) acc[u] += sx[u * 128 + k0 + kk] * w;
            }
        }
#pragma unroll
        for (int u = 0; u < RPB; u++) shid[u * 256 + j] = acc[u];
    }
    __syncthreads();

    // ---- msg = x + hid @ W2 + b2 ----
    {
        int j = tid & 127, half = tid >> 7;
        float acc[RPB];
#pragma unroll
        for (int u = 0; u < RPB; u++) acc[u] = 0.f;
        for (int t = 0; t < 4; t++) {
            __syncthreads();
            for (int i = tid; i < 8192; i += 256) {
                int hh = i >> 12, loc = i & 4095, row = loc >> 7, col = loc & 127;
                wt[i] = W2[(hh * 128 + t * 32 + row) * 128 + col];
            }
            __syncthreads();
            const float* w = wt + half * 4096;
            int kbase = half * 128 + t * 32;
#pragma unroll 8
            for (int kk = 0; kk < 32; kk++) {
                float wv = w[kk * 128 + j];
#pragma unroll
                for (int u = 0; u < RPB; u++) acc[u] += shid[u * 256 + kbase + kk] * wv;
            }
        }
        __syncthreads();
        float* red = wt;
#pragma unroll
        for (int u = 0; u < RPB; u++) red[u * 256 + half * 128 + j] = acc[u];
        __syncthreads();
        if (half == 0) {
            float bj = b2[j];
#pragma unroll
            for (int u = 0; u < RPB; u++)
                smsg[u * 128 + j] = sx[u * 128 + j] + bj + red[u * 256 + j] + red[u * 256 + 128 + j];
        }
    }
    __syncthreads();

    // ---- P_side = msg @ Wr_side -> fp16 chunked [side*4 + (j>>6)][rel][j&63] ----
    {
        int j = tid;
        for (int side = 0; side < 2; side++) {
            float acc[RPB];
#pragma unroll
            for (int u = 0; u < RPB; u++) acc[u] = 0.f;
            for (int k0 = 0; k0 < 128; k0 += 32) {
                __syncthreads();
                for (int i = tid; i < 8192; i += 256)
                    wt[i] = Wr[(side * 128 + k0 + (i >> 8)) * 256 + (i & 255)];
                __syncthreads();
#pragma unroll 8
                for (int kk = 0; kk < 32; kk++) {
                    float w = wt[kk * 256 + j];
#pragma unroll
                    for (int u = 0; u < RPB; u++) acc[u] += smsg[u * 128 + k0 + kk] * w;
                }
            }
            int c = (j >> 6) + side * 4, l = j & 63;
#pragma unroll
            for (int u = 0; u < RPB; u++) {
                int r = r0 + u;
                if (r < n_r) g_P16[((size_t)c * n_r + r) * 64 + l] = __float2half_rn(acc[u]);
            }
        }
    }
}

// ---------------- histogram (int4 vectorized, 4 edges/thread) ----------------
__global__ void k_hist(const int* __restrict__ h, const int* __restrict__ t, int E) {
    int i = blockIdx.x * blockDim.x + threadIdx.x;
    int e = i * 4;
    if (e + 3 < E) {
        int4 hv = *(const int4*)(h + e);
        int4 tv = *(const int4*)(t + e);
        atomicAdd(&g_cnt_h[hv.x], 1); atomicAdd(&g_cnt_h[hv.y], 1);
        atomicAdd(&g_cnt_h[hv.z], 1); atomicAdd(&g_cnt_h[hv.w], 1);
        atomicAdd(&g_cnt_t[tv.x], 1); atomicAdd(&g_cnt_t[tv.y], 1);
        atomicAdd(&g_cnt_t[tv.z], 1); atomicAdd(&g_cnt_t[tv.w], 1);
    } else {
        for (int k = e; k < E; k++) {
            atomicAdd(&g_cnt_h[h[k]], 1);
            atomicAdd(&g_cnt_t[t[k]], 1);
        }
    }
}

// ---------------- scan over PADDED counts (multiples of 4 edges) ----------------
__global__ void k_scan1(int n_e) {
    __shared__ int s[1024];
    int y = blockIdx.y;
    const int* cnt = y ? g_cnt_t : g_cnt_h;
    int* st = y ? g_starts_t : g_starts_h;
    int i = blockIdx.x * 1024 + threadIdx.x;
    int v = (i < n_e) ? ((cnt[i] + 3) & ~3) : 0;
    s[threadIdx.x] = v;
    __syncthreads();
    for (int o = 1; o < 1024; o <<= 1) {
        int tv = (threadIdx.x >= (unsigned)o) ? s[threadIdx.x - o] : 0;
        __syncthreads();
        s[threadIdx.x] += tv;
        __syncthreads();
    }
    if (i < n_e) st[i] = s[threadIdx.x];
    if (threadIdx.x == 1023) g_bsum[y][blockIdx.x] = s[1023];
}

// parallel scan of block sums (nb <= 128)
__global__ void k_scan2(int nb) {
    __shared__ int s[128];
    int y = blockIdx.x;
    int tid = threadIdx.x;
    int v = (tid < nb) ? g_bsum[y][tid] : 0;
    s[tid] = v;
    __syncthreads();
    for (int o = 1; o < 128; o <<= 1) {
        int t = (tid >= o) ? s[tid - o] : 0;
        __syncthreads();
        s[tid] += t;
        __syncthreads();
    }
    if (tid < nb) g_bsum[y][tid] = s[tid] - v;   // exclusive
    if (tid == nb - 1) g_bsum[y][nb] = s[tid];   // total
}

__global__ void k_scan3(int n_e, int nb) {
    int y = blockIdx.y;
    const int* cnt = y ? g_cnt_t : g_cnt_h;
    int* st = y ? g_starts_t : g_starts_h;
    int* cur = y ? g_cur_t : g_cur_h;
    int i = blockIdx.x * 1024 + threadIdx.x;
    if (i < n_e) {
        int pc = (cnt[i] + 3) & ~3;
        int ex = st[i] - pc + g_bsum[y][blockIdx.x];
        st[i] = ex;
        cur[i] = ex;
    }
    if (i == 0) st[n_e] = g_bsum[y][nb];
}

// ---------------- place edges + accumulate softmax denominators ----------------
__global__ void k_place(const int* __restrict__ h, const int* __restrict__ t,
                        const int* __restrict__ rel, int E) {
    int e = blockIdx.x * blockDim.x + threadIdx.x;
    if (e >= E) return;
    int hn = h[e], tn = t[e], r = rel[e];
    float sr = g_sr[r];
    float lh = g_sh[hn] + sr; lh = (lh > 0.f) ? lh : 0.01f * lh;
    float lt = g_st[tn] + sr; lt = (lt > 0.f) ? lt : 0.01f * lt;
    float zh = __expf(lh), zt = __expf(lt);
    float ro = __int_as_float(r * 128);
    int ph = atomicAdd(&g_cur_h[hn], 1);
    g_pack_h[ph] = make_float2(zh, ro);
    int pt = atomicAdd(&g_cur_t[tn], 1);
    g_pack_t[pt] = make_float2(zt, ro);
    atomicAdd(&g_sum_h[hn], zh);
    atomicAdd(&g_sum_t[tn], zt);
}

// ---------------- invert denominators ----------------
__global__ void k_inv(int n_e) {
    int n = blockIdx.x * blockDim.x + threadIdx.x;
    if (n < n_e) {
        g_inv_h[n] = 1.f / (g_sum_h[n] + 1e-16f);
        g_inv_t[n] = 1.f / (g_sum_t[n] + 1e-16f);
    }
}

// ---------------- main SpMM: 64 feats/pass (fp16 table), LDG.128 edge-pair loads ---------
// Batch of 8 edges = 4 predicated LDG.128; segments 4-edge aligned so a float4 never
// straddles node validity; zero float4s are inert (z=0, off=0).
__global__ __launch_bounds__(1024, 1) void k_main(const float2* __restrict__ br2,
                                                  float2* __restrict__ out2,
                                                  int n_e, int n_r) {
    extern __shared__ __half sP[];  // n_r * 64 halves = 128000 B
    int pass = blockIdx.x;          // 0..3 feature chunk (64 feats)
    int nslices = gridDim.y;
    int ns_per = (n_e + nslices - 1) / nslices;
    int n0 = blockIdx.y * ns_per;
    int n1 = min(n0 + ns_per, n_e);
    int lane = threadIdx.x & 31;
    int warp = threadIdx.x >> 5;
    int nwarp = blockDim.x >> 5;
    float2 bv = br2[pass * 32 + lane];
    const char* sPb = (const char*)sP + lane * 4;  // this lane's fp16x2 column
    int chunk_halves = n_r * 64;

    // ---- phase A: h side ----
    {
        const uint4* s4 = (const uint4*)(g_P16 + (size_t)pass * chunk_halves);
        uint4* d4 = (uint4*)sP;
        for (int i = threadIdx.x; i < (chunk_halves >> 3); i += blockDim.x) d4[i] = s4[i];
    }
    __syncthreads();
    {
        const float4* __restrict__ p4 = (const float4*)g_pack_h;
        int n = n0 + warp;
        if (n < n1) {
            int s0 = g_starts_h[n] >> 1;       // float4 units
            int s1 = g_starts_h[n + 1] >> 1;
            float inv = g_inv_h[n];
            while (true) {
                int nn = n + nwarp;
                int t0 = 0, t1 = 0; float tinv = 0.f;
                if (nn < n1) { t0 = g_starts_h[nn] >> 1; t1 = g_starts_h[nn + 1] >> 1; tinv = g_inv_h[nn]; }
                float ax = 0.f, ay = 0.f;
                for (int i = s0; i < s1; i += 4) {
#pragma unroll
                    for (int u = 0; u < 4; u++) {
                        int j = i + u;
                        float4 p = (j < s1) ? p4[j] : make_float4(0.f, 0.f, 0.f, 0.f);
                        __half2 h0 = *(const __half2*)(sPb + __float_as_int(p.y));
                        __half2 h1 = *(const __half2*)(sPb + __float_as_int(p.w));
                        float2 v0 = __half22float2(h0);
                        float2 v1 = __half22float2(h1);
                        ax = fmaf(p.x, v0.x, ax);
                        ay = fmaf(p.x, v0.y, ay);
                        ax = fmaf(p.z, v1.x, ax);
                        ay = fmaf(p.z, v1.y, ay);
                    }
                }
                float2 o;
                o.x = bv.x + ax * inv;
                o.y = bv.y + ay * inv;
                out2[(size_t)n * 128 + pass * 32 + lane] = o;
                if (nn >= n1) break;
                n = nn; s0 = t0; s1 = t1; inv = tinv;
            }
        }
    }
    __syncthreads();

    // ---- phase B: t side (RMW) ----
    {
        const uint4* s4 = (const uint4*)(g_P16 + (size_t)(4 + pass) * chunk_halves);
        uint4* d4 = (uint4*)sP;
        for (int i = threadIdx.x; i < (chunk_halves >> 3); i += blockDim.x) d4[i] = s4[i];
    }
    __syncthreads();
    {
        const float4* __restrict__ p4 = (const float4*)g_pack_t;
        int n = n0 + warp;
        if (n < n1) {
            int s0 = g_starts_t[n] >> 1;
            int s1 = g_starts_t[n + 1] >> 1;
            float inv = g_inv_t[n];
            while (true) {
                int nn = n + nwarp;
                int t0 = 0, t1 = 0; float tinv = 0.f;
                if (nn < n1) { t0 = g_starts_t[nn] >> 1; t1 = g_starts_t[nn + 1] >> 1; tinv = g_inv_t[nn]; }
                float ax = 0.f, ay = 0.f;
                for (int i = s0; i < s1; i += 4) {
#pragma unroll
                    for (int u = 0; u < 4; u++) {
                        int j = i + u;
                        float4 p = (j < s1) ? p4[j] : make_float4(0.f, 0.f, 0.f, 0.f);
                        __half2 h0 = *(const __half2*)(sPb + __float_as_int(p.y));
                        __half2 h1 = *(const __half2*)(sPb + __float_as_int(p.w));
                        float2 v0 = __half22float2(h0);
                        float2 v1 = __half22float2(h1);
                        ax = fmaf(p.x, v0.x, ax);
                        ay = fmaf(p.x, v0.y, ay);
                        ax = fmaf(p.z, v1.x, ax);
                        ay = fmaf(p.z, v1.y, ay);
                    }
                }
                size_t oi = (size_t)n * 128 + pass * 32 + lane;
                float2 o = out2[oi];
                o.x += ax * inv;
                o.y += ay * inv;
                out2[oi] = o;
                if (nn >= n1) break;
                n = nn; s0 = t0; s1 = t1; inv = tinv;
            }
        }
    }
}

// ---------------- launch ----------------
extern "C" void kernel_launch(void* const* d_in, const int* in_sizes, int n_in,
                              void* d_out, int out_size) {
    const float* xe  = (const float*)d_in[0];
    const float* xr  = (const float*)d_in[1];
    const int*   ei  = (const int*)d_in[2];
    const int*   rel = (const int*)d_in[3];
    const float* wah = (const float*)d_in[5];
    const float* wat = (const float*)d_in[6];
    const float* war = (const float*)d_in[7];
    const float* W1  = (const float*)d_in[8];
    const float* b1  = (const float*)d_in[9];
    const float* W2  = (const float*)d_in[10];
    const float* b2  = (const float*)d_in[11];
    const float* Wr  = (const float*)d_in[12];
    const float* br  = (const float*)d_in[13];
    float* out = (float*)d_out;

    int n_e = in_sizes[0] / 128;
    int n_r = in_sizes[1] / 128;
    int E   = in_sizes[3];
    const int* h = ei;
    const int* t = ei + E;
    int nb = (n_e + 1023) / 1024;

    cudaFuncSetAttribute(k_main, cudaFuncAttributeMaxDynamicSharedMemorySize, 131072);

    k_scores<<<((n_e + n_r) * 32 + 255) / 256, 256>>>((const float4*)xe, (const float4*)xr,
                                                      (const float4*)wah, (const float4*)wat,
                                                      (const float4*)war, n_e, n_r);
    k_rgemm<<<(n_r + RPB - 1) / RPB, 256>>>(xr, W1, b1, W2, b2, Wr, n_r);
    k_hist<<<(E / 4 + 256) / 256, 256>>>(h, t, E);
    k_scan1<<<dim3(nb, 2), 1024>>>(n_e);
    k_scan2<<<2, 128>>>(nb);
    k_scan3<<<dim3(nb, 2), 1024>>>(n_e, nb);
    k_place<<<(E + 255) / 256, 256>>>(h, t, rel, E);
    k_inv<<<(n_e + 255) / 256, 256>>>(n_e);

    dim3 g(4, 36);  // 144 blocks, 1/SM (128 KB smem)
    k_main<<<g, 1024, (size_t)n_r * 64 * sizeof(__half)>>>((const float2*)br, (float2*)out, n_e, n_r);
}

// round 8
// speedup vs baseline: 1.1043x; 1.1043x over previous
#include <cuda_runtime.h>
#include <cuda_fp16.h>
#include <math.h>

#define MAX_NE 100000
#define MAX_NR 1000
#define MAX_E  1000000
#define PACK_CAP 1800064   // E + 8*N_E worst-case padding + guard

// ---------------- scratch ----------------
__device__ float  g_sh[MAX_NE];
__device__ float  g_st[MAX_NE];
__device__ float  g_sr[MAX_NR];
// fp16 P tables: [side(2)][chunk(4)][rel][64 halves]; h side 0..3, t side 4..7
__device__ __half g_P16[8 * MAX_NR * 64];
__device__ int    g_cnt_h[MAX_NE];
__device__ int    g_cnt_t[MAX_NE];
__device__ int    g_starts_h[MAX_NE + 1];  // PADDED exclusive starts (multiples of 8 edges)
__device__ int    g_starts_t[MAX_NE + 1];
__device__ int    g_cur_h[MAX_NE];
__device__ int    g_cur_t[MAX_NE];
__device__ float  g_sum_h[MAX_NE];         // softmax denominators (accumulated in k_place)
__device__ float  g_sum_t[MAX_NE];
__device__ float  g_inv_h[MAX_NE];
__device__ float  g_inv_t[MAX_NE];
// pad slots are NEVER written: BSS-zero => {z=0, off=0}, mathematically inert.
__device__ float2 g_pack_h[PACK_CAP];
__device__ float2 g_pack_t[PACK_CAP];
__device__ int    g_bsum[2][160];

// ---------------- fused attention scores + per-node scratch zeroing ----------------
__global__ void k_scores(const float4* __restrict__ xe, const float4* __restrict__ xr,
                         const float4* __restrict__ wah4, const float4* __restrict__ wat4,
                         const float4* __restrict__ war4, int n_e, int n_r) {
    int gw = (blockIdx.x * blockDim.x + threadIdx.x) >> 5;
    int lane = threadIdx.x & 31;
    if (gw < n_e) {
        float4 v = xe[(size_t)gw * 32 + lane];
        float4 a = wah4[lane];
        float4 b = wat4[lane];
        float da = v.x * a.x + v.y * a.y + v.z * a.z + v.w * a.w;
        float db = v.x * b.x + v.y * b.y + v.z * b.z + v.w * b.w;
#pragma unroll
        for (int o = 16; o > 0; o >>= 1) {
            da += __shfl_xor_sync(0xffffffffu, da, o);
            db += __shfl_xor_sync(0xffffffffu, db, o);
        }
        if (lane == 0) { g_sh[gw] = da; g_st[gw] = db; }
        else if (lane == 1) g_cnt_h[gw] = 0;
        else if (lane == 2) g_cnt_t[gw] = 0;
        else if (lane == 3) g_sum_h[gw] = 0.f;
        else if (lane == 4) g_sum_t[gw] = 0.f;
    } else if (gw < n_e + n_r) {
        int r = gw - n_e;
        float4 v = xr[r * 32 + lane];
        float4 a = war4[lane];
        float d = v.x * a.x + v.y * a.y + v.z * a.z + v.w * a.w;
#pragma unroll
        for (int o = 16; o > 0; o >>= 1) d += __shfl_xor_sync(0xffffffffu, d, o);
        if (lane == 0) g_sr[r] = d;
    }
}

// ---------------- fused relation pipeline: x_r -> hid -> msg -> P (fp16) ----------------
#define RPB 8
__global__ __launch_bounds__(256) void k_rgemm(const float* __restrict__ xr,
                                               const float* __restrict__ W1, const float* __restrict__ b1,
                                               const float* __restrict__ W2, const float* __restrict__ b2,
                                               const float* __restrict__ Wr, int n_r) {
    __shared__ float sx[RPB * 128];
    __shared__ float shid[RPB * 256];
    __shared__ float smsg[RPB * 128];
    __shared__ float wt[32 * 256];
    int r0 = blockIdx.x * RPB;
    int tid = threadIdx.x;

    for (int i = tid; i < RPB * 128; i += 256) {
        int rr = i >> 7, k = i & 127, r = r0 + rr;
        sx[i] = (r < n_r) ? xr[r * 128 + k] : 0.f;
    }

    // ---- hid = x @ W1 + b1 ----
    {
        int j = tid;
        float acc[RPB];
        float bj = b1[j];
#pragma unroll
        for (int u = 0; u < RPB; u++) acc[u] = bj;
        for (int k0 = 0; k0 < 128; k0 += 32) {
            __syncthreads();
            for (int i = tid; i < 8192; i += 256)
                wt[i] = W1[(k0 + (i >> 8)) * 256 + (i & 255)];
            __syncthreads();
#pragma unroll 8
            for (int kk = 0; kk < 32; kk++) {
                float w = wt[kk * 256 + j];
#pragma unroll
                for (int u = 0; u < RPB; u++) acc[u] += sx[u * 128 + k0 + kk] * w;
            }
        }
#pragma unroll
        for (int u = 0; u < RPB; u++) shid[u * 256 + j] = acc[u];
    }
    __syncthreads();

    // ---- msg = x + hid @ W2 + b2 ----
    {
        int j = tid & 127, half = tid >> 7;
        float acc[RPB];
#pragma unroll
        for (int u = 0; u < RPB; u++) acc[u] = 0.f;
        for (int t = 0; t < 4; t++) {
            __syncthreads();
            for (int i = tid; i < 8192; i += 256) {
                int hh = i >> 12, loc = i & 4095, row = loc >> 7, col = loc & 127;
                wt[i] = W2[(hh * 128 + t * 32 + row) * 128 + col];
            }
            __syncthreads();
            const float* w = wt + half * 4096;
            int kbase = half * 128 + t * 32;
#pragma unroll 8
            for (int kk = 0; kk < 32; kk++) {
                float wv = w[kk * 128 + j];
#pragma unroll
                for (int u = 0; u < RPB; u++) acc[u] += shid[u * 256 + kbase + kk] * wv;
            }
        }
        __syncthreads();
        float* red = wt;
#pragma unroll
        for (int u = 0; u < RPB; u++) red[u * 256 + half * 128 + j] = acc[u];
        __syncthreads();
        if (half == 0) {
            float bj = b2[j];
#pragma unroll
            for (int u = 0; u < RPB; u++)
                smsg[u * 128 + j] = sx[u * 128 + j] + bj + red[u * 256 + j] + red[u * 256 + 128 + j];
        }
    }
    __syncthreads();

    // ---- P_side = msg @ Wr_side -> fp16 chunked [side*4 + (j>>6)][rel][j&63] ----
    {
        int j = tid;
        for (int side = 0; side < 2; side++) {
            float acc[RPB];
#pragma unroll
            for (int u = 0; u < RPB; u++) acc[u] = 0.f;
            for (int k0 = 0; k0 < 128; k0 += 32) {
                __syncthreads();
                for (int i = tid; i < 8192; i += 256)
                    wt[i] = Wr[(side * 128 + k0 + (i >> 8)) * 256 + (i & 255)];
                __syncthreads();
#pragma unroll 8
                for (int kk = 0; kk < 32; kk++) {
                    float w = wt[kk * 256 + j];
#pragma unroll
                    for (int u = 0; u < RPB; u++) acc[u] += smsg[u * 128 + k0 + kk] * w;
                }
            }
            int c = (j >> 6) + side * 4, l = j & 63;
#pragma unroll
            for (int u = 0; u < RPB; u++) {
                int r = r0 + u;
                if (r < n_r) g_P16[((size_t)c * n_r + r) * 64 + l] = __float2half_rn(acc[u]);
            }
        }
    }
}

// ---------------- histogram (int4 vectorized, 4 edges/thread) ----------------
__global__ void k_hist(const int* __restrict__ h, const int* __restrict__ t, int E) {
    int i = blockIdx.x * blockDim.x + threadIdx.x;
    int e = i * 4;
    if (e + 3 < E) {
        int4 hv = *(const int4*)(h + e);
        int4 tv = *(const int4*)(t + e);
        atomicAdd(&g_cnt_h[hv.x], 1); atomicAdd(&g_cnt_h[hv.y], 1);
        atomicAdd(&g_cnt_h[hv.z], 1); atomicAdd(&g_cnt_h[hv.w], 1);
        atomicAdd(&g_cnt_t[tv.x], 1); atomicAdd(&g_cnt_t[tv.y], 1);
        atomicAdd(&g_cnt_t[tv.z], 1); atomicAdd(&g_cnt_t[tv.w], 1);
    } else {
        for (int k = e; k < E; k++) {
            atomicAdd(&g_cnt_h[h[k]], 1);
            atomicAdd(&g_cnt_t[t[k]], 1);
        }
    }
}

// ---------------- scan over PADDED counts (pad to multiple of 8 edges) ----------------
__global__ void k_scan1(int n_e) {
    __shared__ int s[1024];
    int y = blockIdx.y;
    const int* cnt = y ? g_cnt_t : g_cnt_h;
    int* st = y ? g_starts_t : g_starts_h;
    int i = blockIdx.x * 1024 + threadIdx.x;
    int v = (i < n_e) ? ((cnt[i] + 7) & ~7) : 0;
    s[threadIdx.x] = v;
    __syncthreads();
    for (int o = 1; o < 1024; o <<= 1) {
        int tv = (threadIdx.x >= (unsigned)o) ? s[threadIdx.x - o] : 0;
        __syncthreads();
        s[threadIdx.x] += tv;
        __syncthreads();
    }
    if (i < n_e) st[i] = s[threadIdx.x];
    if (threadIdx.x == 1023) g_bsum[y][blockIdx.x] = s[1023];
}

// parallel scan of block sums (nb <= 128)
__global__ void k_scan2(int nb) {
    __shared__ int s[128];
    int y = blockIdx.x;
    int tid = threadIdx.x;
    int v = (tid < nb) ? g_bsum[y][tid] : 0;
    s[tid] = v;
    __syncthreads();
    for (int o = 1; o < 128; o <<= 1) {
        int t = (tid >= o) ? s[tid - o] : 0;
        __syncthreads();
        s[tid] += t;
        __syncthreads();
    }
    if (tid < nb) g_bsum[y][tid] = s[tid] - v;   // exclusive
    if (tid == nb - 1) g_bsum[y][nb] = s[tid];   // total
}

__global__ void k_scan3(int n_e, int nb) {
    int y = blockIdx.y;
    const int* cnt = y ? g_cnt_t : g_cnt_h;
    int* st = y ? g_starts_t : g_starts_h;
    int* cur = y ? g_cur_t : g_cur_h;
    int i = blockIdx.x * 1024 + threadIdx.x;
    if (i < n_e) {
        int pc = (cnt[i] + 7) & ~7;
        int ex = st[i] - pc + g_bsum[y][blockIdx.x];
        st[i] = ex;
        cur[i] = ex;
    }
    if (i == 0) st[n_e] = g_bsum[y][nb];
}

// ---------------- place edges + accumulate softmax denominators ----------------
__global__ void k_place(const int* __restrict__ h, const int* __restrict__ t,
                        const int* __restrict__ rel, int E) {
    int e = blockIdx.x * blockDim.x + threadIdx.x;
    if (e >= E) return;
    int hn = h[e], tn = t[e], r = rel[e];
    float sr = g_sr[r];
    float lh = g_sh[hn] + sr; lh = (lh > 0.f) ? lh : 0.01f * lh;
    float lt = g_st[tn] + sr; lt = (lt > 0.f) ? lt : 0.01f * lt;
    float zh = __expf(lh), zt = __expf(lt);
    float ro = __int_as_float(r * 128);
    int ph = atomicAdd(&g_cur_h[hn], 1);
    g_pack_h[ph] = make_float2(zh, ro);
    int pt = atomicAdd(&g_cur_t[tn], 1);
    g_pack_t[pt] = make_float2(zt, ro);
    atomicAdd(&g_sum_h[hn], zh);
    atomicAdd(&g_sum_t[tn], zt);
}

// ---------------- invert denominators ----------------
__global__ void k_inv(int n_e) {
    int n = blockIdx.x * blockDim.x + threadIdx.x;
    if (n < n_e) {
        g_inv_h[n] = 1.f / (g_sum_h[n] + 1e-16f);
        g_inv_t[n] = 1.f / (g_sum_t[n] + 1e-16f);
    }
}

// ---------------- main SpMM: 64 feats/pass (fp16 table), 8x UNPREDICATED LDG.64 ----------
// Segments padded to multiples of 8 edges => whole batch always in-segment; pad slots
// are zero {z=0, off=0} so their FFMAs are no-ops. No predication anywhere in the loop.
__global__ __launch_bounds__(1024, 1) void k_main(const float2* __restrict__ br2,
                                                  float2* __restrict__ out2,
                                                  int n_e, int n_r) {
    extern __shared__ __half sP[];  // n_r * 64 halves = 128000 B
    int pass = blockIdx.x;          // 0..3 feature chunk (64 feats)
    int nslices = gridDim.y;
    int ns_per = (n_e + nslices - 1) / nslices;
    int n0 = blockIdx.y * ns_per;
    int n1 = min(n0 + ns_per, n_e);
    int lane = threadIdx.x & 31;
    int warp = threadIdx.x >> 5;
    int nwarp = blockDim.x >> 5;
    float2 bv = br2[pass * 32 + lane];
    const char* sPb = (const char*)sP + lane * 4;  // this lane's fp16x2 column
    int chunk_halves = n_r * 64;

    // ---- phase A: h side ----
    {
        const uint4* s4 = (const uint4*)(g_P16 + (size_t)pass * chunk_halves);
        uint4* d4 = (uint4*)sP;
        for (int i = threadIdx.x; i < (chunk_halves >> 3); i += blockDim.x) d4[i] = s4[i];
    }
    __syncthreads();
    {
        const float2* __restrict__ pk = g_pack_h;
        int n = n0 + warp;
        if (n < n1) {
            int s0 = g_starts_h[n];
            int s1 = g_starts_h[n + 1];
            float inv = g_inv_h[n];
            while (true) {
                int nn = n + nwarp;
                int t0 = 0, t1 = 0; float tinv = 0.f;
                if (nn < n1) { t0 = g_starts_h[nn]; t1 = g_starts_h[nn + 1]; tinv = g_inv_h[nn]; }
                float ax = 0.f, ay = 0.f;
                for (int i = s0; i < s1; i += 8) {
#pragma unroll
                    for (int u = 0; u < 8; u++) {
                        float2 p = pk[i + u];
                        __half2 hv = *(const __half2*)(sPb + __float_as_int(p.y));
                        float2 v = __half22float2(hv);
                        ax = fmaf(p.x, v.x, ax);
                        ay = fmaf(p.x, v.y, ay);
                    }
                }
                float2 o;
                o.x = bv.x + ax * inv;
                o.y = bv.y + ay * inv;
                out2[(size_t)n * 128 + pass * 32 + lane] = o;
                if (nn >= n1) break;
                n = nn; s0 = t0; s1 = t1; inv = tinv;
            }
        }
    }
    __syncthreads();

    // ---- phase B: t side (RMW) ----
    {
        const uint4* s4 = (const uint4*)(g_P16 + (size_t)(4 + pass) * chunk_halves);
        uint4* d4 = (uint4*)sP;
        for (int i = threadIdx.x; i < (chunk_halves >> 3); i += blockDim.x) d4[i] = s4[i];
    }
    __syncthreads();
    {
        const float2* __restrict__ pk = g_pack_t;
        int n = n0 + warp;
        if (n < n1) {
            int s0 = g_starts_t[n];
            int s1 = g_starts_t[n + 1];
            float inv = g_inv_t[n];
            while (true) {
                int nn = n + nwarp;
                int t0 = 0, t1 = 0; float tinv = 0.f;
                if (nn < n1) { t0 = g_starts_t[nn]; t1 = g_starts_t[nn + 1]; tinv = g_inv_t[nn]; }
                float ax = 0.f, ay = 0.f;
                for (int i = s0; i < s1; i += 8) {
#pragma unroll
                    for (int u = 0; u < 8; u++) {
                        float2 p = pk[i + u];
                        __half2 hv = *(const __half2*)(sPb + __float_as_int(p.y));
                        float2 v = __half22float2(hv);
                        ax = fmaf(p.x, v.x, ax);
                        ay = fmaf(p.x, v.y, ay);
                    }
                }
                size_t oi = (size_t)n * 128 + pass * 32 + lane;
                float2 o = out2[oi];
                o.x += ax * inv;
                o.y += ay * inv;
                out2[oi] = o;
                if (nn >= n1) break;
                n = nn; s0 = t0; s1 = t1; inv = tinv;
            }
        }
    }
}

// ---------------- launch ----------------
extern "C" void kernel_launch(void* const* d_in, const int* in_sizes, int n_in,
                              void* d_out, int out_size) {
    const float* xe  = (const float*)d_in[0];
    const float* xr  = (const float*)d_in[1];
    const int*   ei  = (const int*)d_in[2];
    const int*   rel = (const int*)d_in[3];
    const float* wah = (const float*)d_in[5];
    const float* wat = (const float*)d_in[6];
    const float* war = (const float*)d_in[7];
    const float* W1  = (const float*)d_in[8];
    const float* b1  = (const float*)d_in[9];
    const float* W2  = (const float*)d_in[10];
    const float* b2  = (const float*)d_in[11];
    const float* Wr  = (const float*)d_in[12];
    const float* br  = (const float*)d_in[13];
    float* out = (float*)d_out;

    int n_e = in_sizes[0] / 128;
    int n_r = in_sizes[1] / 128;
    int E   = in_sizes[3];
    const int* h = ei;
    const int* t = ei + E;
    int nb = (n_e + 1023) / 1024;

    cudaFuncSetAttribute(k_main, cudaFuncAttributeMaxDynamicSharedMemorySize, 131072);

    k_scores<<<((n_e + n_r) * 32 + 255) / 256, 256>>>((const float4*)xe, (const float4*)xr,
                                                      (const float4*)wah, (const float4*)wat,
                                                      (const float4*)war, n_e, n_r);
    k_rgemm<<<(n_r + RPB - 1) / RPB, 256>>>(xr, W1, b1, W2, b2, Wr, n_r);
    k_hist<<<(E / 4 + 256) / 256, 256>>>(h, t, E);
    k_scan1<<<dim3(nb, 2), 1024>>>(n_e);
    k_scan2<<<2, 128>>>(nb);
    k_scan3<<<dim3(nb, 2), 1024>>>(n_e, nb);
    k_place<<<(E + 255) / 256, 256>>>(h, t, rel, E);
    k_inv<<<(n_e + 255) / 256, 256>>>(n_e);

    dim3 g(4, 36);  // 144 blocks, 1/SM (128 KB smem)
    k_main<<<g, 1024, (size_t)n_r * 64 * sizeof(__half)>>>((const float2*)br, (float2*)out, n_e, n_r);
}

// round 9
// speedup vs baseline: 1.1351x; 1.0279x over previous
#include <cuda_runtime.h>
#include <cuda_fp16.h>
#include <math.h>

#define MAX_NE 100000
#define MAX_NR 1000
#define MAX_E  1000000
#define PACK_CAP 1800064   // generous: E + padding + guard

// ---------------- scratch ----------------
__device__ float  g_sh[MAX_NE];
__device__ float  g_st[MAX_NE];
__device__ float  g_sr[MAX_NR];
// fp16 P tables: [side(2)][chunk(4)][rel][64 halves]; h side 0..3, t side 4..7
__device__ __half g_P16[8 * MAX_NR * 64];
__device__ int    g_cnt_h[MAX_NE];
__device__ int    g_cnt_t[MAX_NE];
__device__ int    g_starts_h[MAX_NE + 1];  // PADDED exclusive starts (multiples of 4 edges)
__device__ int    g_starts_t[MAX_NE + 1];
__device__ int    g_cur_h[MAX_NE];
__device__ int    g_cur_t[MAX_NE];
__device__ float  g_sum_h[MAX_NE];         // softmax denominators (accumulated in k_place)
__device__ float  g_sum_t[MAX_NE];
__device__ float  g_inv_h[MAX_NE];
__device__ float  g_inv_t[MAX_NE];
// pad slots are NEVER written: BSS-zero => {z=0, off=0}, mathematically inert.
__device__ float2 g_pack_h[PACK_CAP];
__device__ float2 g_pack_t[PACK_CAP];
__device__ int    g_bsum[2][160];

// ---------------- fused attention scores + per-node scratch zeroing ----------------
__global__ void k_scores(const float4* __restrict__ xe, const float4* __restrict__ xr,
                         const float4* __restrict__ wah4, const float4* __restrict__ wat4,
                         const float4* __restrict__ war4, int n_e, int n_r) {
    int gw = (blockIdx.x * blockDim.x + threadIdx.x) >> 5;
    int lane = threadIdx.x & 31;
    if (gw < n_e) {
        float4 v = xe[(size_t)gw * 32 + lane];
        float4 a = wah4[lane];
        float4 b = wat4[lane];
        float da = v.x * a.x + v.y * a.y + v.z * a.z + v.w * a.w;
        float db = v.x * b.x + v.y * b.y + v.z * b.z + v.w * b.w;
#pragma unroll
        for (int o = 16; o > 0; o >>= 1) {
            da += __shfl_xor_sync(0xffffffffu, da, o);
            db += __shfl_xor_sync(0xffffffffu, db, o);
        }
        if (lane == 0) { g_sh[gw] = da; g_st[gw] = db; }
        else if (lane == 1) g_cnt_h[gw] = 0;
        else if (lane == 2) g_cnt_t[gw] = 0;
        else if (lane == 3) g_sum_h[gw] = 0.f;
        else if (lane == 4) g_sum_t[gw] = 0.f;
    } else if (gw < n_e + n_r) {
        int r = gw - n_e;
        float4 v = xr[r * 32 + lane];
        float4 a = war4[lane];
        float d = v.x * a.x + v.y * a.y + v.z * a.z + v.w * a.w;
#pragma unroll
        for (int o = 16; o > 0; o >>= 1) d += __shfl_xor_sync(0xffffffffu, d, o);
        if (lane == 0) g_sr[r] = d;
    }
}

// ---------------- fused relation pipeline: x_r -> hid -> msg -> P (fp16) ----------------
#define RPB 8
__global__ __launch_bounds__(256) void k_rgemm(const float* __restrict__ xr,
                                               const float* __restrict__ W1, const float* __restrict__ b1,
                                               const float* __restrict__ W2, const float* __restrict__ b2,
                                               const float* __restrict__ Wr, int n_r) {
    __shared__ float sx[RPB * 128];
    __shared__ float shid[RPB * 256];
    __shared__ float smsg[RPB * 128];
    __shared__ float wt[32 * 256];
    int r0 = blockIdx.x * RPB;
    int tid = threadIdx.x;

    for (int i = tid; i < RPB * 128; i += 256) {
        int rr = i >> 7, k = i & 127, r = r0 + rr;
        sx[i] = (r < n_r) ? xr[r * 128 + k] : 0.f;
    }

    // ---- hid = x @ W1 + b1 ----
    {
        int j = tid;
        float acc[RPB];
        float bj = b1[j];
#pragma unroll
        for (int u = 0; u < RPB; u++) acc[u] = bj;
        for (int k0 = 0; k0 < 128; k0 += 32) {
            __syncthreads();
            for (int i = tid; i < 8192; i += 256)
                wt[i] = W1[(k0 + (i >> 8)) * 256 + (i & 255)];
            __syncthreads();
#pragma unroll 8
            for (int kk = 0; kk < 32; kk++) {
                float w = wt[kk * 256 + j];
#pragma unroll
                for (int u = 0; u < RPB; u++) acc[u] += sx[u * 128 + k0 + kk] * w;
            }
        }
#pragma unroll
        for (int u = 0; u < RPB; u++) shid[u * 256 + j] = acc[u];
    }
    __syncthreads();

    // ---- msg = x + hid @ W2 + b2 ----
    {
        int j = tid & 127, half = tid >> 7;
        float acc[RPB];
#pragma unroll
        for (int u = 0; u < RPB; u++) acc[u] = 0.f;
        for (int t = 0; t < 4; t++) {
            __syncthreads();
            for (int i = tid; i < 8192; i += 256) {
                int hh = i >> 12, loc = i & 4095, row = loc >> 7, col = loc & 127;
                wt[i] = W2[(hh * 128 + t * 32 + row) * 128 + col];
            }
            __syncthreads();
            const float* w = wt + half * 4096;
            int kbase = half * 128 + t * 32;
#pragma unroll 8
            for (int kk = 0; kk < 32; kk++) {
                float wv = w[kk * 128 + j];
#pragma unroll
                for (int u = 0; u < RPB; u++) acc[u] += shid[u * 256 + kbase + kk] * wv;
            }
        }
        __syncthreads();
        float* red = wt;
#pragma unroll
        for (int u = 0; u < RPB; u++) red[u * 256 + half * 128 + j] = acc[u];
        __syncthreads();
        if (half == 0) {
            float bj = b2[j];
#pragma unroll
            for (int u = 0; u < RPB; u++)
                smsg[u * 128 + j] = sx[u * 128 + j] + bj + red[u * 256 + j] + red[u * 256 + 128 + j];
        }
    }
    __syncthreads();

    // ---- P_side = msg @ Wr_side -> fp16 chunked [side*4 + (j>>6)][rel][j&63] ----
    {
        int j = tid;
        for (int side = 0; side < 2; side++) {
            float acc[RPB];
#pragma unroll
            for (int u = 0; u < RPB; u++) acc[u] = 0.f;
            for (int k0 = 0; k0 < 128; k0 += 32) {
                __syncthreads();
                for (int i = tid; i < 8192; i += 256)
                    wt[i] = Wr[(side * 128 + k0 + (i >> 8)) * 256 + (i & 255)];
                __syncthreads();
#pragma unroll 8
                for (int kk = 0; kk < 32; kk++) {
                    float w = wt[kk * 256 + j];
#pragma unroll
                    for (int u = 0; u < RPB; u++) acc[u] += smsg[u * 128 + k0 + kk] * w;
                }
            }
            int c = (j >> 6) + side * 4, l = j & 63;
#pragma unroll
            for (int u = 0; u < RPB; u++) {
                int r = r0 + u;
                if (r < n_r) g_P16[((size_t)c * n_r + r) * 64 + l] = __float2half_rn(acc[u]);
            }
        }
    }
}

// ---------------- histogram (int4 vectorized, 4 edges/thread) ----------------
__global__ void k_hist(const int* __restrict__ h, const int* __restrict__ t, int E) {
    int i = blockIdx.x * blockDim.x + threadIdx.x;
    int e = i * 4;
    if (e + 3 < E) {
        int4 hv = *(const int4*)(h + e);
        int4 tv = *(const int4*)(t + e);
        atomicAdd(&g_cnt_h[hv.x], 1); atomicAdd(&g_cnt_h[hv.y], 1);
        atomicAdd(&g_cnt_h[hv.z], 1); atomicAdd(&g_cnt_h[hv.w], 1);
        atomicAdd(&g_cnt_t[tv.x], 1); atomicAdd(&g_cnt_t[tv.y], 1);
        atomicAdd(&g_cnt_t[tv.z], 1); atomicAdd(&g_cnt_t[tv.w], 1);
    } else {
        for (int k = e; k < E; k++) {
            atomicAdd(&g_cnt_h[h[k]], 1);
            atomicAdd(&g_cnt_t[t[k]], 1);
        }
    }
}

// ---------------- scan over PADDED counts (pad to multiple of 4 edges) ----------------
__global__ void k_scan1(int n_e) {
    __shared__ int s[1024];
    int y = blockIdx.y;
    const int* cnt = y ? g_cnt_t : g_cnt_h;
    int* st = y ? g_starts_t : g_starts_h;
    int i = blockIdx.x * 1024 + threadIdx.x;
    int v = (i < n_e) ? ((cnt[i] + 3) & ~3) : 0;
    s[threadIdx.x] = v;
    __syncthreads();
    for (int o = 1; o < 1024; o <<= 1) {
        int tv = (threadIdx.x >= (unsigned)o) ? s[threadIdx.x - o] : 0;
        __syncthreads();
        s[threadIdx.x] += tv;
        __syncthreads();
    }
    if (i < n_e) st[i] = s[threadIdx.x];
    if (threadIdx.x == 1023) g_bsum[y][blockIdx.x] = s[1023];
}

// parallel scan of block sums (nb <= 128)
__global__ void k_scan2(int nb) {
    __shared__ int s[128];
    int y = blockIdx.x;
    int tid = threadIdx.x;
    int v = (tid < nb) ? g_bsum[y][tid] : 0;
    s[tid] = v;
    __syncthreads();
    for (int o = 1; o < 128; o <<= 1) {
        int t = (tid >= o) ? s[tid - o] : 0;
        __syncthreads();
        s[tid] += t;
        __syncthreads();
    }
    if (tid < nb) g_bsum[y][tid] = s[tid] - v;   // exclusive
    if (tid == nb - 1) g_bsum[y][nb] = s[tid];   // total
}

__global__ void k_scan3(int n_e, int nb) {
    int y = blockIdx.y;
    const int* cnt = y ? g_cnt_t : g_cnt_h;
    int* st = y ? g_starts_t : g_starts_h;
    int* cur = y ? g_cur_t : g_cur_h;
    int i = blockIdx.x * 1024 + threadIdx.x;
    if (i < n_e) {
        int pc = (cnt[i] + 3) & ~3;
        int ex = st[i] - pc + g_bsum[y][blockIdx.x];
        st[i] = ex;
        cur[i] = ex;
    }
    if (i == 0) st[n_e] = g_bsum[y][nb];
}

// ---------------- place edges + accumulate softmax denominators ----------------
__global__ void k_place(const int* __restrict__ h, const int* __restrict__ t,
                        const int* __restrict__ rel, int E) {
    int e = blockIdx.x * blockDim.x + threadIdx.x;
    if (e >= E) return;
    int hn = h[e], tn = t[e], r = rel[e];
    float sr = g_sr[r];
    float lh = g_sh[hn] + sr; lh = (lh > 0.f) ? lh : 0.01f * lh;
    float lt = g_st[tn] + sr; lt = (lt > 0.f) ? lt : 0.01f * lt;
    float zh = __expf(lh), zt = __expf(lt);
    float ro = __int_as_float(r * 128);
    int ph = atomicAdd(&g_cur_h[hn], 1);
    g_pack_h[ph] = make_float2(zh, ro);
    int pt = atomicAdd(&g_cur_t[tn], 1);
    g_pack_t[pt] = make_float2(zt, ro);
    atomicAdd(&g_sum_h[hn], zh);
    atomicAdd(&g_sum_t[tn], zt);
}

// ---------------- invert denominators ----------------
__global__ void k_inv(int n_e) {
    int n = blockIdx.x * blockDim.x + threadIdx.x;
    if (n < n_e) {
        g_inv_h[n] = 1.f / (g_sum_h[n] + 1e-16f);
        g_inv_t[n] = 1.f / (g_sum_t[n] + 1e-16f);
    }
}

// ---------------- main SpMM: 64 feats/pass (fp16 table), TWO-NODE INTERLEAVE ----------
// Each warp processes an adjacent node pair with 4-edge predicated batches per node:
// 8 independent LDG.64 in flight across two independent chains => 2x MLP vs 1-node.
__global__ __launch_bounds__(1024, 1) void k_main(const float2* __restrict__ br2,
                                                  float2* __restrict__ out2,
                                                  int n_e, int n_r) {
    extern __shared__ __half sP[];  // n_r * 64 halves = 128000 B
    int pass = blockIdx.x;          // 0..3 feature chunk (64 feats)
    int nslices = gridDim.y;
    int ns_per = (n_e + nslices - 1) / nslices;
    int n0 = blockIdx.y * ns_per;
    int n1 = min(n0 + ns_per, n_e);
    int lane = threadIdx.x & 31;
    int warp = threadIdx.x >> 5;
    int nwarp = blockDim.x >> 5;
    float2 bv = br2[pass * 32 + lane];
    const char* sPb = (const char*)sP + lane * 4;  // this lane's fp16x2 column
    int chunk_halves = n_r * 64;
    int stp = nwarp << 1;

    // ---- phase A: h side ----
    {
        const uint4* s4 = (const uint4*)(g_P16 + (size_t)pass * chunk_halves);
        uint4* d4 = (uint4*)sP;
        for (int i = threadIdx.x; i < (chunk_halves >> 3); i += blockDim.x) d4[i] = s4[i];
    }
    __syncthreads();
    {
        const float2* __restrict__ pk = g_pack_h;
        int p = n0 + (warp << 1);
        if (p < n1) {
            int a0 = g_starts_h[p];
            int a1 = g_starts_h[p + 1];
            bool hasB = (p + 1 < n1);
            int b1 = hasB ? g_starts_h[p + 2] : a1;   // b segment = [a1, b1)
            float invA = g_inv_h[p];
            float invB = hasB ? g_inv_h[p + 1] : 0.f;
            while (true) {
                int np = p + stp;
                int na0 = 0, na1 = 0, nb1 = 0; float ninvA = 0.f, ninvB = 0.f; bool nHasB = false;
                if (np < n1) {
                    na0 = g_starts_h[np]; na1 = g_starts_h[np + 1];
                    nHasB = (np + 1 < n1);
                    nb1 = nHasB ? g_starts_h[np + 2] : na1;
                    ninvA = g_inv_h[np];
                    ninvB = nHasB ? g_inv_h[np + 1] : 0.f;
                }
                float axA = 0.f, ayA = 0.f, axB = 0.f, ayB = 0.f;
                int lenA = a1 - a0, lenB = b1 - a1;
                int mend = max(lenA, lenB);
                for (int off = 0; off < mend; off += 4) {
#pragma unroll
                    for (int u = 0; u < 4; u++) {
                        int j = a0 + off + u;
                        float2 pa = (j < a1) ? pk[j] : make_float2(0.f, 0.f);
                        int jb = a1 + off + u;
                        float2 pb = (jb < b1) ? pk[jb] : make_float2(0.f, 0.f);
                        __half2 ha = *(const __half2*)(sPb + __float_as_int(pa.y));
                        __half2 hb = *(const __half2*)(sPb + __float_as_int(pb.y));
                        float2 va = __half22float2(ha);
                        float2 vb = __half22float2(hb);
                        axA = fmaf(pa.x, va.x, axA); ayA = fmaf(pa.x, va.y, ayA);
                        axB = fmaf(pb.x, vb.x, axB); ayB = fmaf(pb.x, vb.y, ayB);
                    }
                }
                float2 oA;
                oA.x = bv.x + axA * invA;
                oA.y = bv.y + ayA * invA;
                out2[(size_t)p * 128 + pass * 32 + lane] = oA;
                if (hasB) {
                    float2 oB;
                    oB.x = bv.x + axB * invB;
                    oB.y = bv.y + ayB * invB;
                    out2[(size_t)(p + 1) * 128 + pass * 32 + lane] = oB;
                }
                if (np >= n1) break;
                p = np; a0 = na0; a1 = na1; b1 = nb1; hasB = nHasB; invA = ninvA; invB = ninvB;
            }
        }
    }
    __syncthreads();

    // ---- phase B: t side (RMW) ----
    {
        const uint4* s4 = (const uint4*)(g_P16 + (size_t)(4 + pass) * chunk_halves);
        uint4* d4 = (uint4*)sP;
        for (int i = threadIdx.x; i < (chunk_halves >> 3); i += blockDim.x) d4[i] = s4[i];
    }
    __syncthreads();
    {
        const float2* __restrict__ pk = g_pack_t;
        int p = n0 + (warp << 1);
        if (p < n1) {
            int a0 = g_starts_t[p];
            int a1 = g_starts_t[p + 1];
            bool hasB = (p + 1 < n1);
            int b1 = hasB ? g_starts_t[p + 2] : a1;
            float invA = g_inv_t[p];
            float invB = hasB ? g_inv_t[p + 1] : 0.f;
            while (true) {
                int np = p + stp;
                int na0 = 0, na1 = 0, nb1 = 0; float ninvA = 0.f, ninvB = 0.f; bool nHasB = false;
                if (np < n1) {
                    na0 = g_starts_t[np]; na1 = g_starts_t[np + 1];
                    nHasB = (np + 1 < n1);
                    nb1 = nHasB ? g_starts_t[np + 2] : na1;
                    ninvA = g_inv_t[np];
                    ninvB = nHasB ? g_inv_t[np + 1] : 0.f;
                }
                float axA = 0.f, ayA = 0.f, axB = 0.f, ayB = 0.f;
                int lenA = a1 - a0, lenB = b1 - a1;
                int mend = max(lenA, lenB);
                for (int off = 0; off < mend; off += 4) {
#pragma unroll
                    for (int u = 0; u < 4; u++) {
                        int j = a0 + off + u;
                        float2 pa = (j < a1) ? pk[j] : make_float2(0.f, 0.f);
                        int jb = a1 + off + u;
                        float2 pb = (jb < b1) ? pk[jb] : make_float2(0.f, 0.f);
                        __half2 ha = *(const __half2*)(sPb + __float_as_int(pa.y));
                        __half2 hb = *(const __half2*)(sPb + __float_as_int(pb.y));
                        float2 va = __half22float2(ha);
                        float2 vb = __half22float2(hb);
                        axA = fmaf(pa.x, va.x, axA); ayA = fmaf(pa.x, va.y, ayA);
                        axB = fmaf(pb.x, vb.x, axB); ayB = fmaf(pb.x, vb.y, ayB);
                    }
                }
                size_t oiA = (size_t)p * 128 + pass * 32 + lane;
                float2 oA = out2[oiA];
                oA.x += axA * invA;
                oA.y += ayA * invA;
                out2[oiA] = oA;
                if (hasB) {
                    size_t oiB = (size_t)(p + 1) * 128 + pass * 32 + lane;
                    float2 oB = out2[oiB];
                    oB.x += axB * invB;
                    oB.y += ayB * invB;
                    out2[oiB] = oB;
                }
                if (np >= n1) break;
                p = np; a0 = na0; a1 = na1; b1 = nb1; hasB = nHasB; invA = ninvA; invB = ninvB;
            }
        }
    }
}

// ---------------- launch ----------------
extern "C" void kernel_launch(void* const* d_in, const int* in_sizes, int n_in,
                              void* d_out, int out_size) {
    const float* xe  = (const float*)d_in[0];
    const float* xr  = (const float*)d_in[1];
    const int*   ei  = (const int*)d_in[2];
    const int*   rel = (const int*)d_in[3];
    const float* wah = (const float*)d_in[5];
    const float* wat = (const float*)d_in[6];
    const float* war = (const float*)d_in[7];
    const float* W1  = (const float*)d_in[8];
    const float* b1  = (const float*)d_in[9];
    const float* W2  = (const float*)d_in[10];
    const float* b2  = (const float*)d_in[11];
    const float* Wr  = (const float*)d_in[12];
    const float* br  = (const float*)d_in[13];
    float* out = (float*)d_out;

    int n_e = in_sizes[0] / 128;
    int n_r = in_sizes[1] / 128;
    int E   = in_sizes[3];
    const int* h = ei;
    const int* t = ei + E;
    int nb = (n_e + 1023) / 1024;

    cudaFuncSetAttribute(k_main, cudaFuncAttributeMaxDynamicSharedMemorySize, 131072);

    k_scores<<<((n_e + n_r) * 32 + 255) / 256, 256>>>((const float4*)xe, (const float4*)xr,
                                                      (const float4*)wah, (const float4*)wat,
                                                      (const float4*)war, n_e, n_r);
    k_rgemm<<<(n_r + RPB - 1) / RPB, 256>>>(xr, W1, b1, W2, b2, Wr, n_r);
    k_hist<<<(E / 4 + 256) / 256, 256>>>(h, t, E);
    k_scan1<<<dim3(nb, 2), 1024>>>(n_e);
    k_scan2<<<2, 128>>>(nb);
    k_scan3<<<dim3(nb, 2), 1024>>>(n_e, nb);
    k_place<<<(E + 255) / 256, 256>>>(h, t, rel, E);
    k_inv<<<(n_e + 255) / 256, 256>>>(n_e);

    dim3 g(4, 36);  // 144 blocks, 1/SM (128 KB smem)
    k_main<<<g, 1024, (size_t)n_r * 64 * sizeof(__half)>>>((const float2*)br, (float2*)out, n_e, n_r);
}

// round 10
// speedup vs baseline: 1.4839x; 1.3073x over previous
#include <cuda_runtime.h>
#include <cuda_fp16.h>
#include <math.h>

#define MAX_NE 100000
#define MAX_NR 1000
#define MAX_E  1000000
#define PACK_CAP 1800064   // E + padding + guard

// ---------------- scratch ----------------
__device__ float  g_sh[MAX_NE];
__device__ float  g_st[MAX_NE];
__device__ float  g_sr[MAX_NR];
// fp16 P tables: [side(2)][rel][256]; 512B per row, L2-resident (1 MB total)
__device__ __half g_P16[2 * MAX_NR * 256];
__device__ int    g_cnt_h[MAX_NE];
__device__ int    g_cnt_t[MAX_NE];
__device__ int    g_starts_h[MAX_NE + 1];  // PADDED exclusive starts (multiples of 4 edges)
__device__ int    g_starts_t[MAX_NE + 1];
__device__ int    g_cur_h[MAX_NE];
__device__ int    g_cur_t[MAX_NE];
__device__ float  g_sum_h[MAX_NE];
__device__ float  g_sum_t[MAX_NE];
__device__ float  g_inv_h[MAX_NE];
__device__ float  g_inv_t[MAX_NE];
// pad slots are NEVER written: BSS-zero => {z=0, off=0} -> loads P row 0, FFMA x0 = inert.
__device__ float2 g_pack_h[PACK_CAP];
__device__ float2 g_pack_t[PACK_CAP];
__device__ int    g_bsum[2][160];

// ---------------- fused attention scores + per-node scratch zeroing ----------------
__global__ void k_scores(const float4* __restrict__ xe, const float4* __restrict__ xr,
                         const float4* __restrict__ wah4, const float4* __restrict__ wat4,
                         const float4* __restrict__ war4, int n_e, int n_r) {
    int gw = (blockIdx.x * blockDim.x + threadIdx.x) >> 5;
    int lane = threadIdx.x & 31;
    if (gw < n_e) {
        float4 v = xe[(size_t)gw * 32 + lane];
        float4 a = wah4[lane];
        float4 b = wat4[lane];
        float da = v.x * a.x + v.y * a.y + v.z * a.z + v.w * a.w;
        float db = v.x * b.x + v.y * b.y + v.z * b.z + v.w * b.w;
#pragma unroll
        for (int o = 16; o > 0; o >>= 1) {
            da += __shfl_xor_sync(0xffffffffu, da, o);
            db += __shfl_xor_sync(0xffffffffu, db, o);
        }
        if (lane == 0) { g_sh[gw] = da; g_st[gw] = db; }
        else if (lane == 1) g_cnt_h[gw] = 0;
        else if (lane == 2) g_cnt_t[gw] = 0;
        else if (lane == 3) g_sum_h[gw] = 0.f;
        else if (lane == 4) g_sum_t[gw] = 0.f;
    } else if (gw < n_e + n_r) {
        int r = gw - n_e;
        float4 v = xr[r * 32 + lane];
        float4 a = war4[lane];
        float d = v.x * a.x + v.y * a.y + v.z * a.z + v.w * a.w;
#pragma unroll
        for (int o = 16; o > 0; o >>= 1) d += __shfl_xor_sync(0xffffffffu, d, o);
        if (lane == 0) g_sr[r] = d;
    }
}

// ---------------- fused relation pipeline: x_r -> hid -> msg -> P (fp16, row-major) -----
#define RPB 8
__global__ __launch_bounds__(256) void k_rgemm(const float* __restrict__ xr,
                                               const float* __restrict__ W1, const float* __restrict__ b1,
                                               const float* __restrict__ W2, const float* __restrict__ b2,
                                               const float* __restrict__ Wr, int n_r) {
    __shared__ float sx[RPB * 128];
    __shared__ float shid[RPB * 256];
    __shared__ float smsg[RPB * 128];
    __shared__ float wt[32 * 256];
    int r0 = blockIdx.x * RPB;
    int tid = threadIdx.x;

    for (int i = tid; i < RPB * 128; i += 256) {
        int rr = i >> 7, k = i & 127, r = r0 + rr;
        sx[i] = (r < n_r) ? xr[r * 128 + k] : 0.f;
    }

    // ---- hid = x @ W1 + b1 ----
    {
        int j = tid;
        float acc[RPB];
        float bj = b1[j];
#pragma unroll
        for (int u = 0; u < RPB; u++) acc[u] = bj;
        for (int k0 = 0; k0 < 128; k0 += 32) {
            __syncthreads();
            for (int i = tid; i < 8192; i += 256)
                wt[i] = W1[(k0 + (i >> 8)) * 256 + (i & 255)];
            __syncthreads();
#pragma unroll 8
            for (int kk = 0; kk < 32; kk++) {
                float w = wt[kk * 256 + j];
#pragma unroll
                for (int u = 0; u < RPB; u++) acc[u] += sx[u * 128 + k0 + kk] * w;
            }
        }
#pragma unroll
        for (int u = 0; u < RPB; u++) shid[u * 256 + j] = acc[u];
    }
    __syncthreads();

    // ---- msg = x + hid @ W2 + b2 ----
    {
        int j = tid & 127, half = tid >> 7;
        float acc[RPB];
#pragma unroll
        for (int u = 0; u < RPB; u++) acc[u] = 0.f;
        for (int t = 0; t < 4; t++) {
            __syncthreads();
            for (int i = tid; i < 8192; i += 256) {
                int hh = i >> 12, loc = i & 4095, row = loc >> 7, col = loc & 127;
                wt[i] = W2[(hh * 128 + t * 32 + row) * 128 + col];
            }
            __syncthreads();
            const float* w = wt + half * 4096;
            int kbase = half * 128 + t * 32;
#pragma unroll 8
            for (int kk = 0; kk < 32; kk++) {
                float wv = w[kk * 128 + j];
#pragma unroll
                for (int u = 0; u < RPB; u++) acc[u] += shid[u * 256 + kbase + kk] * wv;
            }
        }
        __syncthreads();
        float* red = wt;
#pragma unroll
        for (int u = 0; u < RPB; u++) red[u * 256 + half * 128 + j] = acc[u];
        __syncthreads();
        if (half == 0) {
            float bj = b2[j];
#pragma unroll
            for (int u = 0; u < RPB; u++)
                smsg[u * 128 + j] = sx[u * 128 + j] + bj + red[u * 256 + j] + red[u * 256 + 128 + j];
        }
    }
    __syncthreads();

    // ---- P_side[r][j] = (msg @ Wr_side)[r][j], fp16 row-major ----
    {
        int j = tid;
        for (int side = 0; side < 2; side++) {
            float acc[RPB];
#pragma unroll
            for (int u = 0; u < RPB; u++) acc[u] = 0.f;
            for (int k0 = 0; k0 < 128; k0 += 32) {
                __syncthreads();
                for (int i = tid; i < 8192; i += 256)
                    wt[i] = Wr[(side * 128 + k0 + (i >> 8)) * 256 + (i & 255)];
                __syncthreads();
#pragma unroll 8
                for (int kk = 0; kk < 32; kk++) {
                    float w = wt[kk * 256 + j];
#pragma unroll
                    for (int u = 0; u < RPB; u++) acc[u] += smsg[u * 128 + k0 + kk] * w;
                }
            }
#pragma unroll
            for (int u = 0; u < RPB; u++) {
                int r = r0 + u;
                if (r < n_r) g_P16[((size_t)side * n_r + r) * 256 + j] = __float2half_rn(acc[u]);
            }
        }
    }
}

// ---------------- histogram (int4 vectorized, 4 edges/thread) ----------------
__global__ void k_hist(const int* __restrict__ h, const int* __restrict__ t, int E) {
    int i = blockIdx.x * blockDim.x + threadIdx.x;
    int e = i * 4;
    if (e + 3 < E) {
        int4 hv = *(const int4*)(h + e);
        int4 tv = *(const int4*)(t + e);
        atomicAdd(&g_cnt_h[hv.x], 1); atomicAdd(&g_cnt_h[hv.y], 1);
        atomicAdd(&g_cnt_h[hv.z], 1); atomicAdd(&g_cnt_h[hv.w], 1);
        atomicAdd(&g_cnt_t[tv.x], 1); atomicAdd(&g_cnt_t[tv.y], 1);
        atomicAdd(&g_cnt_t[tv.z], 1); atomicAdd(&g_cnt_t[tv.w], 1);
    } else {
        for (int k = e; k < E; k++) {
            atomicAdd(&g_cnt_h[h[k]], 1);
            atomicAdd(&g_cnt_t[t[k]], 1);
        }
    }
}

// ---------------- scan over PADDED counts (pad to multiple of 4 edges) ----------------
__global__ void k_scan1(int n_e) {
    __shared__ int s[1024];
    int y = blockIdx.y;
    const int* cnt = y ? g_cnt_t : g_cnt_h;
    int* st = y ? g_starts_t : g_starts_h;
    int i = blockIdx.x * 1024 + threadIdx.x;
    int v = (i < n_e) ? ((cnt[i] + 3) & ~3) : 0;
    s[threadIdx.x] = v;
    __syncthreads();
    for (int o = 1; o < 1024; o <<= 1) {
        int tv = (threadIdx.x >= (unsigned)o) ? s[threadIdx.x - o] : 0;
        __syncthreads();
        s[threadIdx.x] += tv;
        __syncthreads();
    }
    if (i < n_e) st[i] = s[threadIdx.x];
    if (threadIdx.x == 1023) g_bsum[y][blockIdx.x] = s[1023];
}

// parallel scan of block sums (nb <= 128)
__global__ void k_scan2(int nb) {
    __shared__ int s[128];
    int y = blockIdx.x;
    int tid = threadIdx.x;
    int v = (tid < nb) ? g_bsum[y][tid] : 0;
    s[tid] = v;
    __syncthreads();
    for (int o = 1; o < 128; o <<= 1) {
        int t = (tid >= o) ? s[tid - o] : 0;
        __syncthreads();
        s[tid] += t;
        __syncthreads();
    }
    if (tid < nb) g_bsum[y][tid] = s[tid] - v;   // exclusive
    if (tid == nb - 1) g_bsum[y][nb] = s[tid];   // total
}

__global__ void k_scan3(int n_e, int nb) {
    int y = blockIdx.y;
    const int* cnt = y ? g_cnt_t : g_cnt_h;
    int* st = y ? g_starts_t : g_starts_h;
    int* cur = y ? g_cur_t : g_cur_h;
    int i = blockIdx.x * 1024 + threadIdx.x;
    if (i < n_e) {
        int pc = (cnt[i] + 3) & ~3;
        int ex = st[i] - pc + g_bsum[y][blockIdx.x];
        st[i] = ex;
        cur[i] = ex;
    }
    if (i == 0) st[n_e] = g_bsum[y][nb];
}

// ---------------- place edges (off = BYTE offset r*512 into a P side table) ------------
__global__ void k_place(const int* __restrict__ h, const int* __restrict__ t,
                        const int* __restrict__ rel, int E) {
    int e = blockIdx.x * blockDim.x + threadIdx.x;
    if (e >= E) return;
    int hn = h[e], tn = t[e], r = rel[e];
    float sr = g_sr[r];
    float lh = g_sh[hn] + sr; lh = (lh > 0.f) ? lh : 0.01f * lh;
    float lt = g_st[tn] + sr; lt = (lt > 0.f) ? lt : 0.01f * lt;
    float zh = __expf(lh), zt = __expf(lt);
    float ro = __int_as_float(r * 512);
    int ph = atomicAdd(&g_cur_h[hn], 1);
    g_pack_h[ph] = make_float2(zh, ro);
    int pt = atomicAdd(&g_cur_t[tn], 1);
    g_pack_t[pt] = make_float2(zt, ro);
    atomicAdd(&g_sum_h[hn], zh);
    atomicAdd(&g_sum_t[tn], zt);
}

// ---------------- invert denominators ----------------
__global__ void k_inv(int n_e) {
    int n = blockIdx.x * blockDim.x + threadIdx.x;
    if (n < n_e) {
        g_inv_h[n] = 1.f / (g_sum_h[n] + 1e-16f);
        g_inv_t[n] = 1.f / (g_sum_t[n] + 1e-16f);
    }
}

// ---------------- main SpMM: SINGLE PASS, no smem, L2-resident P rows ----------------
// Warp per node; per edge one coalesced LDG.128/lane fetches the full 512B P row
// (8 feats/lane). h and t sides accumulate in registers; out written exactly once.
__global__ __launch_bounds__(256) void k_main(const float* __restrict__ br,
                                              float* __restrict__ out,
                                              int n_e, int n_r) {
    int gw = (blockIdx.x * blockDim.x + threadIdx.x) >> 5;
    int lane = threadIdx.x & 31;
    if (gw >= n_e) return;
    int n = gw;

    const char* Pb = (const char*)g_P16 + lane * 16;   // this lane's 16B of each row
    const char* Pt = Pb + (size_t)n_r * 512;

    float res[8];
    {
        float4 b0 = *(const float4*)(br + lane * 8);
        float4 b1 = *(const float4*)(br + lane * 8 + 4);
        res[0] = b0.x; res[1] = b0.y; res[2] = b0.z; res[3] = b0.w;
        res[4] = b1.x; res[5] = b1.y; res[6] = b1.z; res[7] = b1.w;
    }

    // ---- h side ----
    {
        int s0 = g_starts_h[n], s1 = g_starts_h[n + 1];
        float inv = g_inv_h[n];
        float acc[8];
#pragma unroll
        for (int k = 0; k < 8; k++) acc[k] = 0.f;
        const float2* __restrict__ pk = g_pack_h;
        for (int i = s0; i < s1; i += 4) {
#pragma unroll
            for (int u = 0; u < 4; u++) {
                float2 p = pk[i + u];                       // unpredicated: 4-pad
                uint4 rv = *(const uint4*)(Pb + __float_as_int(p.y));
                float2 v0 = __half22float2(*(const __half2*)&rv.x);
                float2 v1 = __half22float2(*(const __half2*)&rv.y);
                float2 v2 = __half22float2(*(const __half2*)&rv.z);
                float2 v3 = __half22float2(*(const __half2*)&rv.w);
                acc[0] = fmaf(p.x, v0.x, acc[0]); acc[1] = fmaf(p.x, v0.y, acc[1]);
                acc[2] = fmaf(p.x, v1.x, acc[2]); acc[3] = fmaf(p.x, v1.y, acc[3]);
                acc[4] = fmaf(p.x, v2.x, acc[4]); acc[5] = fmaf(p.x, v2.y, acc[5]);
                acc[6] = fmaf(p.x, v3.x, acc[6]); acc[7] = fmaf(p.x, v3.y, acc[7]);
            }
        }
#pragma unroll
        for (int k = 0; k < 8; k++) res[k] = fmaf(acc[k], inv, res[k]);
    }

    // ---- t side ----
    {
        int s0 = g_starts_t[n], s1 = g_starts_t[n + 1];
        float inv = g_inv_t[n];
        float acc[8];
#pragma unroll
        for (int k = 0; k < 8; k++) acc[k] = 0.f;
        const float2* __restrict__ pk = g_pack_t;
        for (int i = s0; i < s1; i += 4) {
#pragma unroll
            for (int u = 0; u < 4; u++) {
                float2 p = pk[i + u];
                uint4 rv = *(const uint4*)(Pt + __float_as_int(p.y));
                float2 v0 = __half22float2(*(const __half2*)&rv.x);
                float2 v1 = __half22float2(*(const __half2*)&rv.y);
                float2 v2 = __half22float2(*(const __half2*)&rv.z);
                float2 v3 = __half22float2(*(const __half2*)&rv.w);
                acc[0] = fmaf(p.x, v0.x, acc[0]); acc[1] = fmaf(p.x, v0.y, acc[1]);
                acc[2] = fmaf(p.x, v1.x, acc[2]); acc[3] = fmaf(p.x, v1.y, acc[3]);
                acc[4] = fmaf(p.x, v2.x, acc[4]); acc[5] = fmaf(p.x, v2.y, acc[5]);
                acc[6] = fmaf(p.x, v3.x, acc[6]); acc[7] = fmaf(p.x, v3.y, acc[7]);
            }
        }
#pragma unroll
        for (int k = 0; k < 8; k++) res[k] = fmaf(acc[k], inv, res[k]);
    }

    // ---- single coalesced store: 1 KB per warp ----
    float* o = out + (size_t)n * 256 + lane * 8;
    *(float4*)o = make_float4(res[0], res[1], res[2], res[3]);
    *(float4*)(o + 4) = make_float4(res[4], res[5], res[6], res[7]);
}

// ---------------- launch ----------------
extern "C" void kernel_launch(void* const* d_in, const int* in_sizes, int n_in,
                              void* d_out, int out_size) {
    const float* xe  = (const float*)d_in[0];
    const float* xr  = (const float*)d_in[1];
    const int*   ei  = (const int*)d_in[2];
    const int*   rel = (const int*)d_in[3];
    const float* wah = (const float*)d_in[5];
    const float* wat = (const float*)d_in[6];
    const float* war = (const float*)d_in[7];
    const float* W1  = (const float*)d_in[8];
    const float* b1  = (const float*)d_in[9];
    const float* W2  = (const float*)d_in[10];
    const float* b2  = (const float*)d_in[11];
    const float* Wr  = (const float*)d_in[12];
    const float* br  = (const float*)d_in[13];
    float* out = (float*)d_out;

    int n_e = in_sizes[0] / 128;
    int n_r = in_sizes[1] / 128;
    int E   = in_sizes[3];
    const int* h = ei;
    const int* t = ei + E;
    int nb = (n_e + 1023) / 1024;

    k_scores<<<((n_e + n_r) * 32 + 255) / 256, 256>>>((const float4*)xe, (const float4*)xr,
                                                      (const float4*)wah, (const float4*)wat,
                                                      (const float4*)war, n_e, n_r);
    k_rgemm<<<(n_r + RPB - 1) / RPB, 256>>>(xr, W1, b1, W2, b2, Wr, n_r);
    k_hist<<<(E / 4 + 256) / 256, 256>>>(h, t, E);
    k_scan1<<<dim3(nb, 2), 1024>>>(n_e);
    k_scan2<<<2, 128>>>(nb);
    k_scan3<<<dim3(nb, 2), 1024>>>(n_e, nb);
    k_place<<<(E + 255) / 256, 256>>>(h, t, rel, E);
    k_inv<<<(n_e + 255) / 256, 256>>>(n_e);

    k_main<<<(n_e * 32 + 255) / 256, 256>>>(br, out, n_e, n_r);
}

// round 11
// speedup vs baseline: 1.5054x; 1.0145x over previous
#include <cuda_runtime.h>
#include <cuda_fp16.h>
#include <math.h>

#define MAX_NE 100000
#define MAX_NR 1000
#define MAX_E  1000000
#define PACK_CAP 1800064   // E + padding + guard

// ---------------- scratch ----------------
__device__ float  g_sh[MAX_NE];
__device__ float  g_st[MAX_NE];
__device__ float  g_sr[MAX_NR];
// fp16 P tables: [side(2)][rel][256]; 512B per row, L2-resident (1 MB total)
__device__ __half g_P16[2 * MAX_NR * 256];
__device__ int    g_cnt_h[MAX_NE];
__device__ int    g_cnt_t[MAX_NE];
__device__ int    g_starts_h[MAX_NE + 1];  // PADDED exclusive starts (multiples of 4 edges)
__device__ int    g_starts_t[MAX_NE + 1];
__device__ int    g_cur_h[MAX_NE];
__device__ int    g_cur_t[MAX_NE];
// pad slots are NEVER written: BSS-zero => {z=0, off=0} -> loads P row 0, FFMA x0 = inert.
__device__ float2 g_pack_h[PACK_CAP];
__device__ float2 g_pack_t[PACK_CAP];
__device__ int    g_bsum[2][160];

// ---------------- fused attention scores + per-node scratch zeroing ----------------
__global__ void k_scores(const float4* __restrict__ xe, const float4* __restrict__ xr,
                         const float4* __restrict__ wah4, const float4* __restrict__ wat4,
                         const float4* __restrict__ war4, int n_e, int n_r) {
    int gw = (blockIdx.x * blockDim.x + threadIdx.x) >> 5;
    int lane = threadIdx.x & 31;
    if (gw < n_e) {
        float4 v = xe[(size_t)gw * 32 + lane];
        float4 a = wah4[lane];
        float4 b = wat4[lane];
        float da = v.x * a.x + v.y * a.y + v.z * a.z + v.w * a.w;
        float db = v.x * b.x + v.y * b.y + v.z * b.z + v.w * b.w;
#pragma unroll
        for (int o = 16; o > 0; o >>= 1) {
            da += __shfl_xor_sync(0xffffffffu, da, o);
            db += __shfl_xor_sync(0xffffffffu, db, o);
        }
        if (lane == 0) { g_sh[gw] = da; g_st[gw] = db; }
        else if (lane == 1) g_cnt_h[gw] = 0;
        else if (lane == 2) g_cnt_t[gw] = 0;
    } else if (gw < n_e + n_r) {
        int r = gw - n_e;
        float4 v = xr[r * 32 + lane];
        float4 a = war4[lane];
        float d = v.x * a.x + v.y * a.y + v.z * a.z + v.w * a.w;
#pragma unroll
        for (int o = 16; o > 0; o >>= 1) d += __shfl_xor_sync(0xffffffffu, d, o);
        if (lane == 0) g_sr[r] = d;
    }
}

// ---------------- fused relation pipeline: x_r -> hid -> msg -> P (fp16, row-major) -----
#define RPB 8
__global__ __launch_bounds__(256) void k_rgemm(const float* __restrict__ xr,
                                               const float* __restrict__ W1, const float* __restrict__ b1,
                                               const float* __restrict__ W2, const float* __restrict__ b2,
                                               const float* __restrict__ Wr, int n_r) {
    __shared__ float sx[RPB * 128];
    __shared__ float shid[RPB * 256];
    __shared__ float smsg[RPB * 128];
    __shared__ float wt[32 * 256];
    int r0 = blockIdx.x * RPB;
    int tid = threadIdx.x;

    for (int i = tid; i < RPB * 128; i += 256) {
        int rr = i >> 7, k = i & 127, r = r0 + rr;
        sx[i] = (r < n_r) ? xr[r * 128 + k] : 0.f;
    }

    // ---- hid = x @ W1 + b1 ----
    {
        int j = tid;
        float acc[RPB];
        float bj = b1[j];
#pragma unroll
        for (int u = 0; u < RPB; u++) acc[u] = bj;
        for (int k0 = 0; k0 < 128; k0 += 32) {
            __syncthreads();
            for (int i = tid; i < 8192; i += 256)
                wt[i] = W1[(k0 + (i >> 8)) * 256 + (i & 255)];
            __syncthreads();
#pragma unroll 8
            for (int kk = 0; kk < 32; kk++) {
                float w = wt[kk * 256 + j];
#pragma unroll
                for (int u = 0; u < RPB; u++) acc[u] += sx[u * 128 + k0 + kk] * w;
            }
        }
#pragma unroll
        for (int u = 0; u < RPB; u++) shid[u * 256 + j] = acc[u];
    }
    __syncthreads();

    // ---- msg = x + hid @ W2 + b2 ----
    {
        int j = tid & 127, half = tid >> 7;
        float acc[RPB];
#pragma unroll
        for (int u = 0; u < RPB; u++) acc[u] = 0.f;
        for (int t = 0; t < 4; t++) {
            __syncthreads();
            for (int i = tid; i < 8192; i += 256) {
                int hh = i >> 12, loc = i & 4095, row = loc >> 7, col = loc & 127;
                wt[i] = W2[(hh * 128 + t * 32 + row) * 128 + col];
            }
            __syncthreads();
            const float* w = wt + half * 4096;
            int kbase = half * 128 + t * 32;
#pragma unroll 8
            for (int kk = 0; kk < 32; kk++) {
                float wv = w[kk * 128 + j];
#pragma unroll
                for (int u = 0; u < RPB; u++) acc[u] += shid[u * 256 + kbase + kk] * wv;
            }
        }
        __syncthreads();
        float* red = wt;
#pragma unroll
        for (int u = 0; u < RPB; u++) red[u * 256 + half * 128 + j] = acc[u];
        __syncthreads();
        if (half == 0) {
            float bj = b2[j];
#pragma unroll
            for (int u = 0; u < RPB; u++)
                smsg[u * 128 + j] = sx[u * 128 + j] + bj + red[u * 256 + j] + red[u * 256 + 128 + j];
        }
    }
    __syncthreads();

    // ---- P_side[r][j] = (msg @ Wr_side)[r][j], fp16 row-major ----
    {
        int j = tid;
        for (int side = 0; side < 2; side++) {
            float acc[RPB];
#pragma unroll
            for (int u = 0; u < RPB; u++) acc[u] = 0.f;
            for (int k0 = 0; k0 < 128; k0 += 32) {
                __syncthreads();
                for (int i = tid; i < 8192; i += 256)
                    wt[i] = Wr[(side * 128 + k0 + (i >> 8)) * 256 + (i & 255)];
                __syncthreads();
#pragma unroll 8
                for (int kk = 0; kk < 32; kk++) {
                    float w = wt[kk * 256 + j];
#pragma unroll
                    for (int u = 0; u < RPB; u++) acc[u] += smsg[u * 128 + k0 + kk] * w;
                }
            }
#pragma unroll
            for (int u = 0; u < RPB; u++) {
                int r = r0 + u;
                if (r < n_r) g_P16[((size_t)side * n_r + r) * 256 + j] = __float2half_rn(acc[u]);
            }
        }
    }
}

// ---------------- histogram (int4 vectorized, 4 edges/thread) ----------------
__global__ void k_hist(const int* __restrict__ h, const int* __restrict__ t, int E) {
    int i = blockIdx.x * blockDim.x + threadIdx.x;
    int e = i * 4;
    if (e + 3 < E) {
        int4 hv = *(const int4*)(h + e);
        int4 tv = *(const int4*)(t + e);
        atomicAdd(&g_cnt_h[hv.x], 1); atomicAdd(&g_cnt_h[hv.y], 1);
        atomicAdd(&g_cnt_h[hv.z], 1); atomicAdd(&g_cnt_h[hv.w], 1);
        atomicAdd(&g_cnt_t[tv.x], 1); atomicAdd(&g_cnt_t[tv.y], 1);
        atomicAdd(&g_cnt_t[tv.z], 1); atomicAdd(&g_cnt_t[tv.w], 1);
    } else {
        for (int k = e; k < E; k++) {
            atomicAdd(&g_cnt_h[h[k]], 1);
            atomicAdd(&g_cnt_t[t[k]], 1);
        }
    }
}

// ---------------- scan over PADDED counts (pad to multiple of 4 edges) ----------------
__global__ void k_scan1(int n_e) {
    __shared__ int s[1024];
    int y = blockIdx.y;
    const int* cnt = y ? g_cnt_t : g_cnt_h;
    int* st = y ? g_starts_t : g_starts_h;
    int i = blockIdx.x * 1024 + threadIdx.x;
    int v = (i < n_e) ? ((cnt[i] + 3) & ~3) : 0;
    s[threadIdx.x] = v;
    __syncthreads();
    for (int o = 1; o < 1024; o <<= 1) {
        int tv = (threadIdx.x >= (unsigned)o) ? s[threadIdx.x - o] : 0;
        __syncthreads();
        s[threadIdx.x] += tv;
        __syncthreads();
    }
    if (i < n_e) st[i] = s[threadIdx.x];
    if (threadIdx.x == 1023) g_bsum[y][blockIdx.x] = s[1023];
}

// parallel scan of block sums (nb <= 128)
__global__ void k_scan2(int nb) {
    __shared__ int s[128];
    int y = blockIdx.x;
    int tid = threadIdx.x;
    int v = (tid < nb) ? g_bsum[y][tid] : 0;
    s[tid] = v;
    __syncthreads();
    for (int o = 1; o < 128; o <<= 1) {
        int t = (tid >= o) ? s[tid - o] : 0;
        __syncthreads();
        s[tid] += t;
        __syncthreads();
    }
    if (tid < nb) g_bsum[y][tid] = s[tid] - v;   // exclusive
    if (tid == nb - 1) g_bsum[y][nb] = s[tid];   // total
}

__global__ void k_scan3(int n_e, int nb) {
    int y = blockIdx.y;
    const int* cnt = y ? g_cnt_t : g_cnt_h;
    int* st = y ? g_starts_t : g_starts_h;
    int* cur = y ? g_cur_t : g_cur_h;
    int i = blockIdx.x * 1024 + threadIdx.x;
    if (i < n_e) {
        int pc = (cnt[i] + 3) & ~3;
        int ex = st[i] - pc + g_bsum[y][blockIdx.x];
        st[i] = ex;
        cur[i] = ex;
    }
    if (i == 0) st[n_e] = g_bsum[y][nb];
}

// ---------------- place edges (off = BYTE offset r*512), 2 edges/thread ----------------
__global__ void k_place(const int* __restrict__ h, const int* __restrict__ t,
                        const int* __restrict__ rel, int E) {
    int i = blockIdx.x * blockDim.x + threadIdx.x;
    int e = i * 2;
    if (e >= E) return;
    int ne = min(2, E - e);
#pragma unroll
    for (int u = 0; u < 2; u++) {
        if (u < ne) {
            int hn = h[e + u], tn = t[e + u], r = rel[e + u];
            float sr = g_sr[r];
            float lh = g_sh[hn] + sr; lh = (lh > 0.f) ? lh : 0.01f * lh;
            float lt = g_st[tn] + sr; lt = (lt > 0.f) ? lt : 0.01f * lt;
            float zh = __expf(lh), zt = __expf(lt);
            float ro = __int_as_float(r * 512);
            int ph = atomicAdd(&g_cur_h[hn], 1);
            g_pack_h[ph] = make_float2(zh, ro);
            int pt = atomicAdd(&g_cur_t[tn], 1);
            g_pack_t[pt] = make_float2(zt, ro);
        }
    }
}

// ---------------- main SpMM: SINGLE PASS, no smem, L2-resident P rows ----------------
// Warp per node; per edge one coalesced LDG.128/lane fetches the full 512B P row.
// Softmax denominator computed inline from the (warp-uniform) pack stream.
__global__ __launch_bounds__(256) void k_main(const float* __restrict__ br,
                                              float* __restrict__ out,
                                              int n_e, int n_r) {
    int gw = (blockIdx.x * blockDim.x + threadIdx.x) >> 5;
    int lane = threadIdx.x & 31;
    if (gw >= n_e) return;
    int n = gw;

    const char* Pb = (const char*)g_P16 + lane * 16;   // this lane's 16B of each row
    const char* Pt = Pb + (size_t)n_r * 512;

    float res[8];
    {
        float4 b0 = *(const float4*)(br + lane * 8);
        float4 b1 = *(const float4*)(br + lane * 8 + 4);
        res[0] = b0.x; res[1] = b0.y; res[2] = b0.z; res[3] = b0.w;
        res[4] = b1.x; res[5] = b1.y; res[6] = b1.z; res[7] = b1.w;
    }

    // ---- h side ----
    {
        int s0 = g_starts_h[n], s1 = g_starts_h[n + 1];
        float zs = 0.f;
        float acc[8];
#pragma unroll
        for (int k = 0; k < 8; k++) acc[k] = 0.f;
        const float2* __restrict__ pk = g_pack_h;
        for (int i = s0; i < s1; i += 4) {
#pragma unroll
            for (int u = 0; u < 4; u++) {
                float2 p = pk[i + u];                       // unpredicated: 4-pad
                uint4 rv = *(const uint4*)(Pb + __float_as_int(p.y));
                zs += p.x;
                float2 v0 = __half22float2(*(const __half2*)&rv.x);
                float2 v1 = __half22float2(*(const __half2*)&rv.y);
                float2 v2 = __half22float2(*(const __half2*)&rv.z);
                float2 v3 = __half22float2(*(const __half2*)&rv.w);
                acc[0] = fmaf(p.x, v0.x, acc[0]); acc[1] = fmaf(p.x, v0.y, acc[1]);
                acc[2] = fmaf(p.x, v1.x, acc[2]); acc[3] = fmaf(p.x, v1.y, acc[3]);
                acc[4] = fmaf(p.x, v2.x, acc[4]); acc[5] = fmaf(p.x, v2.y, acc[5]);
                acc[6] = fmaf(p.x, v3.x, acc[6]); acc[7] = fmaf(p.x, v3.y, acc[7]);
            }
        }
        float inv = 1.f / (zs + 1e-16f);
#pragma unroll
        for (int k = 0; k < 8; k++) res[k] = fmaf(acc[k], inv, res[k]);
    }

    // ---- t side ----
    {
        int s0 = g_starts_t[n], s1 = g_starts_t[n + 1];
        float zs = 0.f;
        float acc[8];
#pragma unroll
        for (int k = 0; k < 8; k++) acc[k] = 0.f;
        const float2* __restrict__ pk = g_pack_t;
        for (int i = s0; i < s1; i += 4) {
#pragma unroll
            for (int u = 0; u < 4; u++) {
                float2 p = pk[i + u];
                uint4 rv = *(const uint4*)(Pt + __float_as_int(p.y));
                zs += p.x;
                float2 v0 = __half22float2(*(const __half2*)&rv.x);
                float2 v1 = __half22float2(*(const __half2*)&rv.y);
                float2 v2 = __half22float2(*(const __half2*)&rv.z);
                float2 v3 = __half22float2(*(const __half2*)&rv.w);
                acc[0] = fmaf(p.x, v0.x, acc[0]); acc[1] = fmaf(p.x, v0.y, acc[1]);
                acc[2] = fmaf(p.x, v1.x, acc[2]); acc[3] = fmaf(p.x, v1.y, acc[3]);
                acc[4] = fmaf(p.x, v2.x, acc[4]); acc[5] = fmaf(p.x, v2.y, acc[5]);
                acc[6] = fmaf(p.x, v3.x, acc[6]); acc[7] = fmaf(p.x, v3.y, acc[7]);
            }
        }
        float inv = 1.f / (zs + 1e-16f);
#pragma unroll
        for (int k = 0; k < 8; k++) res[k] = fmaf(acc[k], inv, res[k]);
    }

    // ---- single coalesced store: 1 KB per warp ----
    float* o = out + (size_t)n * 256 + lane * 8;
    *(float4*)o = make_float4(res[0], res[1], res[2], res[3]);
    *(float4*)(o + 4) = make_float4(res[4], res[5], res[6], res[7]);
}

// ---------------- launch ----------------
extern "C" void kernel_launch(void* const* d_in, const int* in_sizes, int n_in,
                              void* d_out, int out_size) {
    const float* xe  = (const float*)d_in[0];
    const float* xr  = (const float*)d_in[1];
    const int*   ei  = (const int*)d_in[2];
    const int*   rel = (const int*)d_in[3];
    const float* wah = (const float*)d_in[5];
    const float* wat = (const float*)d_in[6];
    const float* war = (const float*)d_in[7];
    const float* W1  = (const float*)d_in[8];
    const float* b1  = (const float*)d_in[9];
    const float* W2  = (const float*)d_in[10];
    const float* b2  = (const float*)d_in[11];
    const float* Wr  = (const float*)d_in[12];
    const float* br  = (const float*)d_in[13];
    float* out = (float*)d_out;

    int n_e = in_sizes[0] / 128;
    int n_r = in_sizes[1] / 128;
    int E   = in_sizes[3];
    const int* h = ei;
    const int* t = ei + E;
    int nb = (n_e + 1023) / 1024;

    k_scores<<<((n_e + n_r) * 32 + 255) / 256, 256>>>((const float4*)xe, (const float4*)xr,
                                                      (const float4*)wah, (const float4*)wat,
                                                      (const float4*)war, n_e, n_r);
    k_rgemm<<<(n_r + RPB - 1) / RPB, 256>>>(xr, W1, b1, W2, b2, Wr, n_r);
    k_hist<<<(E / 4 + 256) / 256, 256>>>(h, t, E);
    k_scan1<<<dim3(nb, 2), 1024>>>(n_e);
    k_scan2<<<2, 128>>>(nb);
    k_scan3<<<dim3(nb, 2), 1024>>>(n_e, nb);
    k_place<<<(E / 2 + 256) / 256, 256>>>(h, t, rel, E);

    k_main<<<(n_e * 32 + 255) / 256, 256>>>(br, out, n_e, n_r);
}